// round 3
// baseline (speedup 1.0000x reference)
#include <cuda_runtime.h>
#include <cuda_bf16.h>
#include <cstdint>

// ===================== problem constants =====================
#define NTOK  16384          // B*N tokens
#define DIM   1024
#define EDIM  3072           // 3*DIM
#define BATCH 4
#define SEQ   4096
#define NSEG  32
#define SEGL  128            // SEQ / NSEG

// ===================== device scratch (no cudaMalloc allowed) ==========
__device__ __nv_bfloat16 g_hhi[(size_t)NTOK * DIM];
__device__ __nv_bfloat16 g_hlo[(size_t)NTOK * DIM];
__device__ __nv_bfloat16 g_whi[(size_t)EDIM * DIM];
__device__ __nv_bfloat16 g_wlo[(size_t)EDIM * DIM];
__device__ float         g_qkva[(size_t)NTOK * EDIM];   // GEMM out; scan A rewrites kv/a in place
__device__ float         g_sumA[BATCH * NSEG * DIM];
__device__ float         g_sumY[BATCH * NSEG * DIM];
__device__ float         g_carry[BATCH * NSEG * DIM];

// ===================== PTX helpers (all valid on compute_103) ==========
__device__ __forceinline__ uint32_t smem_u32(const void* p) {
    uint32_t r;
    asm("{ .reg .u64 t; cvta.to.shared.u64 t, %1; cvt.u32.u64 %0, t; }" : "=r"(r) : "l"(p));
    return r;
}
__device__ __forceinline__ void cp16(uint32_t dst, const void* src) {
    asm volatile("cp.async.cg.shared.global [%0], [%1], 16;" :: "r"(dst), "l"(src));
}
#define CP_COMMIT() asm volatile("cp.async.commit_group;" ::: "memory")
#define CP_WAIT2()  asm volatile("cp.async.wait_group 2;" ::: "memory")

__device__ __forceinline__ void ldm_x4(uint32_t* r, uint32_t addr) {
    asm volatile("ldmatrix.sync.aligned.m8n8.x4.shared.b16 {%0,%1,%2,%3}, [%4];"
                 : "=r"(r[0]), "=r"(r[1]), "=r"(r[2]), "=r"(r[3]) : "r"(addr));
}
__device__ __forceinline__ void ldm_x2(uint32_t* r, uint32_t addr) {
    asm volatile("ldmatrix.sync.aligned.m8n8.x2.shared.b16 {%0,%1}, [%2];"
                 : "=r"(r[0]), "=r"(r[1]) : "r"(addr));
}
__device__ __forceinline__ void mma16816(float* c, const uint32_t* a, const uint32_t* b) {
    asm volatile(
        "mma.sync.aligned.m16n8k16.row.col.f32.bf16.bf16.f32 "
        "{%0,%1,%2,%3}, {%4,%5,%6,%7}, {%8,%9}, {%0,%1,%2,%3};"
        : "+f"(c[0]), "+f"(c[1]), "+f"(c[2]), "+f"(c[3])
        : "r"(a[0]), "r"(a[1]), "r"(a[2]), "r"(a[3]), "r"(b[0]), "r"(b[1]));
}

// ===================== kernel 1: RMSNorm + fp32 -> (bf16 hi, lo) split =====================
__global__ void rmsnorm_split_kernel(const float* __restrict__ x, const float* __restrict__ gamma) {
    __shared__ float red[8];
    const int tok = blockIdx.x;
    const int tid = threadIdx.x;   // 256 threads, 4 elems each
    float4 v = ((const float4*)(x + (size_t)tok * DIM))[tid];
    float s = v.x * v.x + v.y * v.y + v.z * v.z + v.w * v.w;
    #pragma unroll
    for (int o = 16; o; o >>= 1) s += __shfl_xor_sync(0xffffffffu, s, o);
    if ((tid & 31) == 0) red[tid >> 5] = s;
    __syncthreads();
    if (tid == 0) {
        float t = 0.f;
        #pragma unroll
        for (int i = 0; i < 8; i++) t += red[i];
        red[0] = 32.0f / fmaxf(sqrtf(t), 1e-12f);   // sqrt(DIM)=32
    }
    __syncthreads();
    const float scl = red[0];
    float4 g = ((const float4*)gamma)[tid];
    float h0 = v.x * scl * g.x, h1 = v.y * scl * g.y;
    float h2 = v.z * scl * g.z, h3 = v.w * scl * g.w;
    __nv_bfloat162 hi01 = __floats2bfloat162_rn(h0, h1);
    __nv_bfloat162 hi23 = __floats2bfloat162_rn(h2, h3);
    float l0 = h0 - __bfloat162float(__low2bfloat16(hi01));
    float l1 = h1 - __bfloat162float(__high2bfloat16(hi01));
    float l2 = h2 - __bfloat162float(__low2bfloat16(hi23));
    float l3 = h3 - __bfloat162float(__high2bfloat16(hi23));
    __nv_bfloat162 lo01 = __floats2bfloat162_rn(l0, l1);
    __nv_bfloat162 lo23 = __floats2bfloat162_rn(l2, l3);
    __nv_bfloat162* hh = (__nv_bfloat162*)(g_hhi + (size_t)tok * DIM);
    __nv_bfloat162* hl = (__nv_bfloat162*)(g_hlo + (size_t)tok * DIM);
    hh[2 * tid] = hi01; hh[2 * tid + 1] = hi23;
    hl[2 * tid] = lo01; hl[2 * tid + 1] = lo23;
}

// ===================== kernel 2: weight split =====================
__global__ void wsplit_kernel(const float* __restrict__ w) {
    size_t i4 = (size_t)blockIdx.x * 256 + threadIdx.x;   // EDIM*DIM/4 float4s
    float4 v = ((const float4*)w)[i4];
    __nv_bfloat162 hi01 = __floats2bfloat162_rn(v.x, v.y);
    __nv_bfloat162 hi23 = __floats2bfloat162_rn(v.z, v.w);
    float l0 = v.x - __bfloat162float(__low2bfloat16(hi01));
    float l1 = v.y - __bfloat162float(__high2bfloat16(hi01));
    float l2 = v.z - __bfloat162float(__low2bfloat16(hi23));
    float l3 = v.w - __bfloat162float(__high2bfloat16(hi23));
    ((__nv_bfloat162*)g_whi)[2 * i4]     = hi01;
    ((__nv_bfloat162*)g_whi)[2 * i4 + 1] = hi23;
    ((__nv_bfloat162*)g_wlo)[2 * i4]     = __floats2bfloat162_rn(l0, l1);
    ((__nv_bfloat162*)g_wlo)[2 * i4 + 1] = __floats2bfloat162_rn(l2, l3);
}

// ===================== kernel 3: HMMA GEMM (mma.sync bf16, split-hi/lo, fp32 acc) ==========
// qkva[m][e] = sum_d h[m][d]*w[e][d]; CTA tile 128x128, BK=32, 4-stage cp.async ring.
// SMEM stage: Ahi/Alo/Bhi/Blo, each 128 rows x 32 bf16, pitch 40 bf16 (80 B).
#define PITCHB 80
#define TILEB  (128 * PITCHB)          // 10240
#define OFF_AHI 0
#define OFF_ALO (1 * TILEB)
#define OFF_BHI (2 * TILEB)
#define OFF_BLO (3 * TILEB)
#define STAGEB  (4 * TILEB)            // 40960
#define NSTAGE  4
#define GEMM_SMEM (NSTAGE * STAGEB)    // 163840

__device__ __forceinline__ void load_stage(uint32_t sm_stage,
                                           const __nv_bfloat16* Ah, const __nv_bfloat16* Al,
                                           const __nv_bfloat16* Bh, const __nv_bfloat16* Bl,
                                           int koff, int tid) {
    #pragma unroll
    for (int i = 0; i < 2; i++) {
        const int c   = tid + i * 256;       // 0..511
        const int row = c >> 2;
        const int kc  = c & 3;
        const uint32_t so = (uint32_t)(row * PITCHB + kc * 16);
        const size_t   go = (size_t)row * DIM + koff + kc * 8;
        cp16(sm_stage + OFF_AHI + so, Ah + go);
        cp16(sm_stage + OFF_ALO + so, Al + go);
        cp16(sm_stage + OFF_BHI + so, Bh + go);
        cp16(sm_stage + OFF_BLO + so, Bl + go);
    }
}

__global__ void __launch_bounds__(256) gemm_kernel() {
    extern __shared__ char smem[];
    const uint32_t smem_base = smem_u32(smem);
    const int tid  = threadIdx.x;
    const int wid  = tid >> 5;
    const int lane = tid & 31;
    const int warp_m = wid >> 2;     // 0..1  -> 64-row strip
    const int warp_n = wid & 3;      // 0..3  -> 32-col strip
    const int ntile = blockIdx.x;    // 0..23
    const int mtile = blockIdx.y;    // 0..127

    const __nv_bfloat16* Ah = g_hhi + (size_t)(mtile * 128) * DIM;
    const __nv_bfloat16* Al = g_hlo + (size_t)(mtile * 128) * DIM;
    const __nv_bfloat16* Bh = g_whi + (size_t)(ntile * 128) * DIM;
    const __nv_bfloat16* Bl = g_wlo + (size_t)(ntile * 128) * DIM;

    // prologue: stages 0..2
    #pragma unroll
    for (int s = 0; s < NSTAGE - 1; s++) {
        load_stage(smem_base + s * STAGEB, Ah, Al, Bh, Bl, s * 32, tid);
        CP_COMMIT();
    }

    float acc[4][4][4];
    #pragma unroll
    for (int mt = 0; mt < 4; mt++)
        #pragma unroll
        for (int nt = 0; nt < 4; nt++)
            #pragma unroll
            for (int r = 0; r < 4; r++) acc[mt][nt][r] = 0.f;

    for (int kc = 0; kc < 32; kc++) {
        CP_WAIT2();                   // stage kc loaded (<=2 groups pending)
        __syncthreads();
        // issue loads for kc+3 into the slot freed by kc-1
        if (kc + NSTAGE - 1 < 32)
            load_stage(smem_base + ((kc + NSTAGE - 1) & (NSTAGE - 1)) * STAGEB,
                       Ah, Al, Bh, Bl, (kc + NSTAGE - 1) * 32, tid);
        CP_COMMIT();

        const uint32_t sb = smem_base + (kc & (NSTAGE - 1)) * STAGEB;
        #pragma unroll
        for (int step = 0; step < 2; step++) {
            uint32_t ah[4][4], al_[4][4], bh[4][2], bl[4][2];
            const uint32_t a_off = sb + (uint32_t)((warp_m * 64 + (lane & 15)) * PITCHB)
                                      + step * 32 + ((lane >> 4) << 4);
            #pragma unroll
            for (int mt = 0; mt < 4; mt++) {
                ldm_x4(ah[mt],  a_off + OFF_AHI + mt * 16 * PITCHB);
                ldm_x4(al_[mt], a_off + OFF_ALO + mt * 16 * PITCHB);
            }
            const uint32_t b_off = sb + (uint32_t)((warp_n * 32 + (lane & 7)) * PITCHB)
                                      + step * 32 + (((lane >> 3) & 1) << 4);
            #pragma unroll
            for (int nt = 0; nt < 4; nt++) {
                ldm_x2(bh[nt], b_off + OFF_BHI + nt * 8 * PITCHB);
                ldm_x2(bl[nt], b_off + OFF_BLO + nt * 8 * PITCHB);
            }
            #pragma unroll
            for (int mt = 0; mt < 4; mt++)
                #pragma unroll
                for (int nt = 0; nt < 4; nt++) {
                    mma16816(acc[mt][nt], ah[mt],  bh[nt]);
                    mma16816(acc[mt][nt], ah[mt],  bl[nt]);
                    mma16816(acc[mt][nt], al_[mt], bh[nt]);
                }
        }
    }

    // epilogue: direct fp32 stores
    const int gid = lane >> 2, qid = lane & 3;
    #pragma unroll
    for (int mt = 0; mt < 4; mt++) {
        const int row0 = mtile * 128 + warp_m * 64 + mt * 16 + gid;
        #pragma unroll
        for (int nt = 0; nt < 4; nt++) {
            const int col = ntile * 128 + warp_n * 32 + nt * 8 + qid * 2;
            float2 v0 = make_float2(acc[mt][nt][0], acc[mt][nt][1]);
            float2 v1 = make_float2(acc[mt][nt][2], acc[mt][nt][3]);
            *(float2*)(g_qkva + (size_t)row0 * EDIM + col)       = v0;
            *(float2*)(g_qkva + (size_t)(row0 + 8) * EDIM + col) = v1;
        }
    }
}

// ===================== kernel 4: scan pass A (local scans, sigmoid fused) =====================
__global__ void scanA_kernel() {
    const int d   = blockIdx.x * 128 + threadIdx.x;   // 0..1023
    const int seg = blockIdx.y;
    const int b   = blockIdx.z;
    const size_t base_tok = (size_t)b * SEQ + (size_t)seg * SEGL;
    float pa = 1.0f, y = 0.0f;
    for (int i = 0; i < SEGL; i++) {
        const size_t off = (base_tok + i) * EDIM;
        const float kv = g_qkva[off + DIM + d];
        const float av = g_qkva[off + 2 * DIM + d];
        const float a  = 1.0f / (1.0f + expf(-av));
        y  = a * y + kv;
        pa *= a;
        g_qkva[off + DIM + d]     = y;    // local inclusive scan
        g_qkva[off + 2 * DIM + d] = pa;   // prefix product of gates
    }
    const int sidx = (b * NSEG + seg) * DIM + d;
    g_sumA[sidx] = pa;
    g_sumY[sidx] = y;
}

// ===================== kernel 5: scan pass B (segment-summary scan) =====================
__global__ void scanB_kernel() {
    const int b = blockIdx.x;
    const int d = threadIdx.x;    // 1024 threads
    float cy = 0.0f;
    for (int s = 0; s < NSEG; s++) {
        const int idx = (b * NSEG + s) * DIM + d;
        g_carry[idx] = cy;                      // carry entering segment s
        cy = g_sumA[idx] * cy + g_sumY[idx];
    }
}

// ===================== kernel 6: scan pass C (combine + q*y) =====================
__global__ void scanC_kernel(float* __restrict__ out) {
    const size_t idx = (size_t)blockIdx.x * 256 + threadIdx.x;  // NTOK*DIM elems
    const int d      = (int)(idx & (DIM - 1));
    const size_t tok = idx >> 10;
    const int n      = (int)(tok & (SEQ - 1));
    const int b      = (int)(tok >> 12);
    const int seg    = n >> 7;
    const size_t off = tok * EDIM;
    const float q  = g_qkva[off + d];
    const float yl = g_qkva[off + DIM + d];
    const float pa = g_qkva[off + 2 * DIM + d];
    const float c  = g_carry[(b * NSEG + seg) * DIM + d];
    out[idx] = q * (yl + pa * c);
}

// ===================== launcher =====================
extern "C" void kernel_launch(void* const* d_in, const int* in_sizes, int n_in,
                              void* d_out, int out_size) {
    const float* x     = (const float*)d_in[0];   // [4,4096,1024] f32
    const float* w     = (const float*)d_in[1];   // [3072,1024]  f32
    const float* gamma = (const float*)d_in[2];   // [1024]       f32
    float* out = (float*)d_out;

    cudaFuncSetAttribute(gemm_kernel, cudaFuncAttributeMaxDynamicSharedMemorySize, GEMM_SMEM);

    rmsnorm_split_kernel<<<NTOK, 256>>>(x, gamma);
    wsplit_kernel<<<(EDIM * DIM / 4) / 256, 256>>>(w);
    gemm_kernel<<<dim3(EDIM / 128, NTOK / 128), 256, GEMM_SMEM>>>();
    scanA_kernel<<<dim3(DIM / 128, NSEG, BATCH), 128>>>();
    scanB_kernel<<<BATCH, DIM>>>();
    scanC_kernel<<<(NTOK * DIM) / 256, 256>>>(out);
}

// round 4
// speedup vs baseline: 1.0392x; 1.0392x over previous
#include <cuda_runtime.h>
#include <cuda_bf16.h>
#include <cstdint>

// ===================== problem constants =====================
#define NTOK  16384          // B*N tokens
#define DIM   1024
#define EDIM  3072           // 3*DIM
#define BATCH 4
#define SEQ   4096
#define NSEG  32
#define SEGL  128            // SEQ / NSEG

// ===================== device scratch (no cudaMalloc allowed) ==========
__device__ __nv_bfloat16 g_hhi[(size_t)NTOK * DIM];
__device__ __nv_bfloat16 g_hlo[(size_t)NTOK * DIM];
__device__ __nv_bfloat16 g_whi[(size_t)EDIM * DIM];
__device__ __nv_bfloat16 g_wlo[(size_t)EDIM * DIM];
__device__ float         g_qkva[(size_t)NTOK * EDIM];   // GEMM output [tok][3d]
__device__ float         g_carry[BATCH * NSEG * DIM];   // inclusive carries per segment
__device__ int           g_sflag[BATCH * NSEG * (DIM / 256)];

// ===================== PTX helpers (all valid on compute_103) ==========
__device__ __forceinline__ uint32_t smem_u32(const void* p) {
    uint32_t r;
    asm("{ .reg .u64 t; cvta.to.shared.u64 t, %1; cvt.u32.u64 %0, t; }" : "=r"(r) : "l"(p));
    return r;
}
__device__ __forceinline__ void cp16(uint32_t dst, const void* src) {
    asm volatile("cp.async.cg.shared.global [%0], [%1], 16;" :: "r"(dst), "l"(src));
}
#define CP_COMMIT() asm volatile("cp.async.commit_group;" ::: "memory")
#define CP_WAIT2()  asm volatile("cp.async.wait_group 2;" ::: "memory")

__device__ __forceinline__ void ldm_x4(uint32_t* r, uint32_t addr) {
    asm volatile("ldmatrix.sync.aligned.m8n8.x4.shared.b16 {%0,%1,%2,%3}, [%4];"
                 : "=r"(r[0]), "=r"(r[1]), "=r"(r[2]), "=r"(r[3]) : "r"(addr));
}
__device__ __forceinline__ void ldm_x2(uint32_t* r, uint32_t addr) {
    asm volatile("ldmatrix.sync.aligned.m8n8.x2.shared.b16 {%0,%1}, [%2];"
                 : "=r"(r[0]), "=r"(r[1]) : "r"(addr));
}
__device__ __forceinline__ void mma16816(float* c, const uint32_t* a, const uint32_t* b) {
    asm volatile(
        "mma.sync.aligned.m16n8k16.row.col.f32.bf16.bf16.f32 "
        "{%0,%1,%2,%3}, {%4,%5,%6,%7}, {%8,%9}, {%0,%1,%2,%3};"
        : "+f"(c[0]), "+f"(c[1]), "+f"(c[2]), "+f"(c[3])
        : "r"(a[0]), "r"(a[1]), "r"(a[2]), "r"(a[3]), "r"(b[0]), "r"(b[1]));
}

// ===================== kernel 0: clear lookback flags =====================
__global__ void clear_flags_kernel() {
    const int i = blockIdx.x * 128 + threadIdx.x;
    if (i < BATCH * NSEG * (DIM / 256)) g_sflag[i] = 0;
}

// ===================== kernel 1: RMSNorm + fp32 -> (bf16 hi, lo) split =====================
__global__ void rmsnorm_split_kernel(const float* __restrict__ x, const float* __restrict__ gamma) {
    __shared__ float red[8];
    const int tok = blockIdx.x;
    const int tid = threadIdx.x;   // 256 threads, 4 elems each
    float4 v = ((const float4*)(x + (size_t)tok * DIM))[tid];
    float s = v.x * v.x + v.y * v.y + v.z * v.z + v.w * v.w;
    #pragma unroll
    for (int o = 16; o; o >>= 1) s += __shfl_xor_sync(0xffffffffu, s, o);
    if ((tid & 31) == 0) red[tid >> 5] = s;
    __syncthreads();
    if (tid == 0) {
        float t = 0.f;
        #pragma unroll
        for (int i = 0; i < 8; i++) t += red[i];
        red[0] = 32.0f / fmaxf(sqrtf(t), 1e-12f);   // sqrt(DIM)=32
    }
    __syncthreads();
    const float scl = red[0];
    float4 g = ((const float4*)gamma)[tid];
    float h0 = v.x * scl * g.x, h1 = v.y * scl * g.y;
    float h2 = v.z * scl * g.z, h3 = v.w * scl * g.w;
    __nv_bfloat162 hi01 = __floats2bfloat162_rn(h0, h1);
    __nv_bfloat162 hi23 = __floats2bfloat162_rn(h2, h3);
    float l0 = h0 - __bfloat162float(__low2bfloat16(hi01));
    float l1 = h1 - __bfloat162float(__high2bfloat16(hi01));
    float l2 = h2 - __bfloat162float(__low2bfloat16(hi23));
    float l3 = h3 - __bfloat162float(__high2bfloat16(hi23));
    __nv_bfloat162* hh = (__nv_bfloat162*)(g_hhi + (size_t)tok * DIM);
    __nv_bfloat162* hl = (__nv_bfloat162*)(g_hlo + (size_t)tok * DIM);
    hh[2 * tid] = hi01; hh[2 * tid + 1] = hi23;
    hl[2 * tid] = __floats2bfloat162_rn(l0, l1);
    hl[2 * tid + 1] = __floats2bfloat162_rn(l2, l3);
}

// ===================== kernel 2: weight split =====================
__global__ void wsplit_kernel(const float* __restrict__ w) {
    size_t i4 = (size_t)blockIdx.x * 256 + threadIdx.x;   // EDIM*DIM/4 float4s
    float4 v = ((const float4*)w)[i4];
    __nv_bfloat162 hi01 = __floats2bfloat162_rn(v.x, v.y);
    __nv_bfloat162 hi23 = __floats2bfloat162_rn(v.z, v.w);
    float l0 = v.x - __bfloat162float(__low2bfloat16(hi01));
    float l1 = v.y - __bfloat162float(__high2bfloat16(hi01));
    float l2 = v.z - __bfloat162float(__low2bfloat16(hi23));
    float l3 = v.w - __bfloat162float(__high2bfloat16(hi23));
    ((__nv_bfloat162*)g_whi)[2 * i4]     = hi01;
    ((__nv_bfloat162*)g_whi)[2 * i4 + 1] = hi23;
    ((__nv_bfloat162*)g_wlo)[2 * i4]     = __floats2bfloat162_rn(l0, l1);
    ((__nv_bfloat162*)g_wlo)[2 * i4 + 1] = __floats2bfloat162_rn(l2, l3);
}

// ===================== kernel 3: HMMA GEMM, 2 CTAs/SM ==========
// qkva[m][e] = sum_d h[m][d]*w[e][d]; CTA tile 128x128, BK=16, 4-stage cp.async ring.
// SMEM stage: Ahi/Alo/Bhi/Blo each 128 rows x 16 bf16, pitch 48 B (conflict-free ldmatrix).
#define PITCHB 48
#define TILEB  (128 * PITCHB)          // 6144
#define OFF_AHI 0
#define OFF_ALO (1 * TILEB)
#define OFF_BHI (2 * TILEB)
#define OFF_BLO (3 * TILEB)
#define STAGEB  (4 * TILEB)            // 24576
#define NSTAGE  4
#define NKC     64                     // 1024 / 16
#define GEMM_SMEM (NSTAGE * STAGEB)    // 98304 -> 2 CTAs/SM

__device__ __forceinline__ void load_stage(uint32_t sm_stage,
                                           const __nv_bfloat16* Ah, const __nv_bfloat16* Al,
                                           const __nv_bfloat16* Bh, const __nv_bfloat16* Bl,
                                           int koff, int tid) {
    const int row = tid >> 1;            // 0..127
    const int ch  = tid & 1;             // 0..1  (two 16B chunks per 32B row)
    const uint32_t so = (uint32_t)(row * PITCHB + ch * 16);
    const size_t   go = (size_t)row * DIM + koff + ch * 8;
    cp16(sm_stage + OFF_AHI + so, Ah + go);
    cp16(sm_stage + OFF_ALO + so, Al + go);
    cp16(sm_stage + OFF_BHI + so, Bh + go);
    cp16(sm_stage + OFF_BLO + so, Bl + go);
}

__global__ void __launch_bounds__(256, 2) gemm_kernel() {
    extern __shared__ char smem[];
    const uint32_t smem_base = smem_u32(smem);
    const int tid  = threadIdx.x;
    const int wid  = tid >> 5;
    const int lane = tid & 31;
    const int warp_m = wid >> 2;     // 0..1  -> 64-row strip
    const int warp_n = wid & 3;      // 0..3  -> 32-col strip
    const int ntile = blockIdx.x;    // 0..23  (fast dim -> A shared in L2)
    const int mtile = blockIdx.y;    // 0..127

    const __nv_bfloat16* Ah = g_hhi + (size_t)(mtile * 128) * DIM;
    const __nv_bfloat16* Al = g_hlo + (size_t)(mtile * 128) * DIM;
    const __nv_bfloat16* Bh = g_whi + (size_t)(ntile * 128) * DIM;
    const __nv_bfloat16* Bl = g_wlo + (size_t)(ntile * 128) * DIM;

    // prologue: stages 0..2
    #pragma unroll
    for (int s = 0; s < NSTAGE - 1; s++) {
        load_stage(smem_base + s * STAGEB, Ah, Al, Bh, Bl, s * 16, tid);
        CP_COMMIT();
    }

    float acc[4][4][4];
    #pragma unroll
    for (int mt = 0; mt < 4; mt++)
        #pragma unroll
        for (int nt = 0; nt < 4; nt++)
            #pragma unroll
            for (int r = 0; r < 4; r++) acc[mt][nt][r] = 0.f;

    // precomputed intra-stage fragment offsets
    const uint32_t a_base = (uint32_t)((warp_m * 64 + (lane & 15)) * PITCHB) + ((lane >> 4) << 4);
    const uint32_t b_base = (uint32_t)((warp_n * 32 + (lane & 7)) * PITCHB) + (((lane >> 3) & 1) << 4);

    for (int kc = 0; kc < NKC; kc++) {
        CP_WAIT2();                      // stage kc resident (<=2 groups in flight)
        __syncthreads();
        if (kc + NSTAGE - 1 < NKC)       // refill the slot freed by compute(kc-1)
            load_stage(smem_base + ((kc + NSTAGE - 1) & (NSTAGE - 1)) * STAGEB,
                       Ah, Al, Bh, Bl, (kc + NSTAGE - 1) * 16, tid);
        CP_COMMIT();

        const uint32_t sb = smem_base + (kc & (NSTAGE - 1)) * STAGEB;
        uint32_t ah[4][4], al_[4][4];
        #pragma unroll
        for (int mt = 0; mt < 4; mt++) {
            ldm_x4(ah[mt],  sb + OFF_AHI + a_base + mt * 16 * PITCHB);
            ldm_x4(al_[mt], sb + OFF_ALO + a_base + mt * 16 * PITCHB);
        }
        #pragma unroll
        for (int nt = 0; nt < 4; nt++) {
            uint32_t bh[2], bl[2];
            ldm_x2(bh, sb + OFF_BHI + b_base + nt * 8 * PITCHB);
            ldm_x2(bl, sb + OFF_BLO + b_base + nt * 8 * PITCHB);
            #pragma unroll
            for (int mt = 0; mt < 4; mt++) {
                mma16816(acc[mt][nt], ah[mt],  bh);
                mma16816(acc[mt][nt], ah[mt],  bl);
                mma16816(acc[mt][nt], al_[mt], bh);
            }
        }
    }

    // epilogue: direct fp32 stores
    const int gid = lane >> 2, qid = lane & 3;
    #pragma unroll
    for (int mt = 0; mt < 4; mt++) {
        const int row0 = mtile * 128 + warp_m * 64 + mt * 16 + gid;
        #pragma unroll
        for (int nt = 0; nt < 4; nt++) {
            const int col = ntile * 128 + warp_n * 32 + nt * 8 + qid * 2;
            *(float2*)(g_qkva + (size_t)row0 * EDIM + col)       = make_float2(acc[mt][nt][0], acc[mt][nt][1]);
            *(float2*)(g_qkva + (size_t)(row0 + 8) * EDIM + col) = make_float2(acc[mt][nt][2], acc[mt][nt][3]);
        }
    }
}

// ===================== kernel 4: fused scan (chained carry lookback) =====================
// grid (DIM/256, NSEG, BATCH), 128 threads, 2 channels per thread (float2).
// pass1: local scan -> (pa_seg, y_seg); publish inclusive carry; wait predecessor;
// pass2: recompute with carry folded in, write out = q * y directly.
__global__ void __launch_bounds__(128) scan_fused_kernel(float* __restrict__ out) {
    const int tid = threadIdx.x;
    const int xc  = blockIdx.x;          // 0..3
    const int seg = blockIdx.y;          // 0..31
    const int b   = blockIdx.z;          // 0..3
    const int d0  = xc * 256 + tid * 2;
    const size_t tok0 = (size_t)b * SEQ + (size_t)seg * SEGL;

    // ---- pass 1: segment-local scan ----
    float pa0 = 1.f, pa1 = 1.f, y0 = 0.f, y1 = 0.f;
    const float* base_kv = g_qkva + tok0 * EDIM + DIM + d0;
    const float* base_av = g_qkva + tok0 * EDIM + 2 * DIM + d0;
    for (int i = 0; i < SEGL; i++) {
        const float2 kv = *(const float2*)(base_kv + (size_t)i * EDIM);
        const float2 av = *(const float2*)(base_av + (size_t)i * EDIM);
        const float a0 = 1.0f / (1.0f + __expf(-av.x));
        const float a1 = 1.0f / (1.0f + __expf(-av.y));
        y0 = a0 * y0 + kv.x;  pa0 *= a0;
        y1 = a1 * y1 + kv.y;  pa1 *= a1;
    }

    // ---- lookback: wait predecessor's inclusive carry, publish ours ----
    const int fstride = DIM / 256;                    // 4
    const int fidx = (b * NSEG + seg) * fstride + xc;
    float c0 = 0.f, c1 = 0.f;
    if (seg > 0) {
        const int* flagp = &g_sflag[fidx - fstride];
        if (tid == 0) {
            unsigned v;
            do {
                asm volatile("ld.acquire.gpu.global.b32 %0, [%1];" : "=r"(v) : "l"(flagp) : "memory");
            } while (v == 0);
        }
        __syncthreads();
        const float2 cp = *(const float2*)&g_carry[(size_t)(b * NSEG + seg - 1) * DIM + d0];
        c0 = cp.x; c1 = cp.y;
    }
    // inclusive carry for this segment
    float2 cinc = make_float2(pa0 * c0 + y0, pa1 * c1 + y1);
    if (seg < NSEG - 1) {
        *(float2*)&g_carry[(size_t)(b * NSEG + seg) * DIM + d0] = cinc;
        __threadfence();
        __syncthreads();
        if (tid == 0) {
            asm volatile("st.release.gpu.global.b32 [%0], %1;" :: "l"(&g_sflag[fidx]), "r"(1) : "memory");
        }
    }

    // ---- pass 2: recompute with carry-in, emit q*y ----
    const float* base_q = g_qkva + tok0 * EDIM + d0;
    float* outp = out + tok0 * DIM + d0;
    y0 = c0; y1 = c1;
    for (int i = 0; i < SEGL; i++) {
        const float2 kv = *(const float2*)(base_kv + (size_t)i * EDIM);
        const float2 av = *(const float2*)(base_av + (size_t)i * EDIM);
        const float2 q  = *(const float2*)(base_q  + (size_t)i * EDIM);
        const float a0 = 1.0f / (1.0f + __expf(-av.x));
        const float a1 = 1.0f / (1.0f + __expf(-av.y));
        y0 = a0 * y0 + kv.x;
        y1 = a1 * y1 + kv.y;
        *(float2*)(outp + (size_t)i * DIM) = make_float2(q.x * y0, q.y * y1);
    }
}

// ===================== launcher =====================
extern "C" void kernel_launch(void* const* d_in, const int* in_sizes, int n_in,
                              void* d_out, int out_size) {
    const float* x     = (const float*)d_in[0];   // [4,4096,1024] f32
    const float* w     = (const float*)d_in[1];   // [3072,1024]  f32
    const float* gamma = (const float*)d_in[2];   // [1024]       f32
    float* out = (float*)d_out;

    cudaFuncSetAttribute(gemm_kernel, cudaFuncAttributeMaxDynamicSharedMemorySize, GEMM_SMEM);

    clear_flags_kernel<<<(BATCH * NSEG * (DIM / 256) + 127) / 128, 128>>>();
    rmsnorm_split_kernel<<<NTOK, 256>>>(x, gamma);
    wsplit_kernel<<<(EDIM * DIM / 4) / 256, 256>>>(w);
    gemm_kernel<<<dim3(EDIM / 128, NTOK / 128), 256, GEMM_SMEM>>>();
    scan_fused_kernel<<<dim3(DIM / 256, NSEG, BATCH), 128>>>(out);
}

// round 5
// speedup vs baseline: 1.4054x; 1.3524x over previous
#include <cuda_runtime.h>
#include <cuda_fp16.h>
#include <cstdint>

// ===================== problem constants =====================
#define NTOK  16384          // B*N tokens
#define DIM   1024
#define EDIM  3072           // 3*DIM
#define BATCH 4
#define SEQ   4096
#define NSEG  32
#define SEGL  128            // SEQ / NSEG

// ===================== device scratch (no cudaMalloc allowed) ==========
__device__ __half g_ha [(size_t)NTOK * DIM];   // fp16 activations (single)
__device__ __half g_whh[(size_t)EDIM * DIM];   // fp16 weight hi
__device__ __half g_wlo[(size_t)EDIM * DIM];   // fp16 weight lo (residual)
__device__ float  g_qkva[(size_t)NTOK * EDIM]; // GEMM output [tok][3d]
__device__ float  g_carry[BATCH * NSEG * DIM]; // inclusive carries per segment
__device__ int    g_sflag[BATCH * NSEG * (DIM / 256)];

// ===================== PTX helpers (all valid on compute_103) ==========
__device__ __forceinline__ uint32_t smem_u32(const void* p) {
    uint32_t r;
    asm("{ .reg .u64 t; cvta.to.shared.u64 t, %1; cvt.u32.u64 %0, t; }" : "=r"(r) : "l"(p));
    return r;
}
__device__ __forceinline__ void cp16(uint32_t dst, const void* src) {
    asm volatile("cp.async.cg.shared.global [%0], [%1], 16;" :: "r"(dst), "l"(src));
}
#define CP_COMMIT() asm volatile("cp.async.commit_group;" ::: "memory")
#define CP_WAIT2()  asm volatile("cp.async.wait_group 2;" ::: "memory")

__device__ __forceinline__ void ldm_x4(uint32_t* r, uint32_t addr) {
    asm volatile("ldmatrix.sync.aligned.m8n8.x4.shared.b16 {%0,%1,%2,%3}, [%4];"
                 : "=r"(r[0]), "=r"(r[1]), "=r"(r[2]), "=r"(r[3]) : "r"(addr));
}
__device__ __forceinline__ void ldm_x2(uint32_t* r, uint32_t addr) {
    asm volatile("ldmatrix.sync.aligned.m8n8.x2.shared.b16 {%0,%1}, [%2];"
                 : "=r"(r[0]), "=r"(r[1]) : "r"(addr));
}
__device__ __forceinline__ void mma16816(float* c, const uint32_t* a, const uint32_t* b) {
    asm volatile(
        "mma.sync.aligned.m16n8k16.row.col.f32.f16.f16.f32 "
        "{%0,%1,%2,%3}, {%4,%5,%6,%7}, {%8,%9}, {%0,%1,%2,%3};"
        : "+f"(c[0]), "+f"(c[1]), "+f"(c[2]), "+f"(c[3])
        : "r"(a[0]), "r"(a[1]), "r"(a[2]), "r"(a[3]), "r"(b[0]), "r"(b[1]));
}

// ===================== kernel 0: clear lookback flags =====================
__global__ void clear_flags_kernel() {
    const int i = blockIdx.x * 128 + threadIdx.x;
    if (i < BATCH * NSEG * (DIM / 256)) g_sflag[i] = 0;
}

// ===================== kernel 1: RMSNorm -> fp16 activations ==============
__global__ void rmsnorm_kernel(const float* __restrict__ x, const float* __restrict__ gamma) {
    __shared__ float red[8];
    const int tok = blockIdx.x;
    const int tid = threadIdx.x;   // 256 threads, 4 elems each
    float4 v = ((const float4*)(x + (size_t)tok * DIM))[tid];
    float s = v.x * v.x + v.y * v.y + v.z * v.z + v.w * v.w;
    #pragma unroll
    for (int o = 16; o; o >>= 1) s += __shfl_xor_sync(0xffffffffu, s, o);
    if ((tid & 31) == 0) red[tid >> 5] = s;
    __syncthreads();
    if (tid == 0) {
        float t = 0.f;
        #pragma unroll
        for (int i = 0; i < 8; i++) t += red[i];
        red[0] = 32.0f / fmaxf(sqrtf(t), 1e-12f);   // sqrt(DIM)=32
    }
    __syncthreads();
    const float scl = red[0];
    float4 g = ((const float4*)gamma)[tid];
    __half2* hh = (__half2*)(g_ha + (size_t)tok * DIM);
    hh[2 * tid]     = __floats2half2_rn(v.x * scl * g.x, v.y * scl * g.y);
    hh[2 * tid + 1] = __floats2half2_rn(v.z * scl * g.z, v.w * scl * g.w);
}

// ===================== kernel 2: weight split (fp16 hi + residual) ========
__global__ void wsplit_kernel(const float* __restrict__ w) {
    size_t i4 = (size_t)blockIdx.x * 256 + threadIdx.x;   // EDIM*DIM/4 float4s
    float4 v = ((const float4*)w)[i4];
    __half h0 = __float2half_rn(v.x), h1 = __float2half_rn(v.y);
    __half h2 = __float2half_rn(v.z), h3 = __float2half_rn(v.w);
    float l0 = v.x - __half2float(h0);
    float l1 = v.y - __half2float(h1);
    float l2 = v.z - __half2float(h2);
    float l3 = v.w - __half2float(h3);
    ((__half2*)g_whh)[2 * i4]     = __halves2half2(h0, h1);
    ((__half2*)g_whh)[2 * i4 + 1] = __halves2half2(h2, h3);
    ((__half2*)g_wlo)[2 * i4]     = __floats2half2_rn(l0, l1);
    ((__half2*)g_wlo)[2 * i4 + 1] = __floats2half2_rn(l2, l3);
}

// ===================== kernel 3: HMMA GEMM (fp16, 2 MMAs/term) ============
// qkva[m][e] = sum_d h[m][d]*w[e][d]; CTA tile 128x128, BK=16, 4-stage cp.async.
// SMEM stage: A / Bhi / Blo, each 128 rows x 16 fp16, pitch 48 B.
#define PITCHB 48
#define TILEB  (128 * PITCHB)          // 6144
#define OFF_A  0
#define OFF_BH (1 * TILEB)
#define OFF_BL (2 * TILEB)
#define STAGEB (3 * TILEB)             // 18432
#define NSTAGE 4
#define NKC    64                      // 1024 / 16
#define GEMM_SMEM (NSTAGE * STAGEB)    // 73728 -> 2 CTAs/SM (reg-bound)

__device__ __forceinline__ void load_stage(uint32_t sm_stage,
                                           const __half* A, const __half* Bh,
                                           const __half* Bl, int koff, int tid) {
    const int row = tid >> 1;            // 0..127
    const int ch  = tid & 1;             // two 16B chunks per 32B row
    const uint32_t so = (uint32_t)(row * PITCHB + ch * 16);
    const size_t   go = (size_t)row * DIM + koff + ch * 8;
    cp16(sm_stage + OFF_A  + so, A  + go);
    cp16(sm_stage + OFF_BH + so, Bh + go);
    cp16(sm_stage + OFF_BL + so, Bl + go);
}

__global__ void __launch_bounds__(256, 2) gemm_kernel() {
    extern __shared__ char smem[];
    const uint32_t smem_base = smem_u32(smem);
    const int tid  = threadIdx.x;
    const int wid  = tid >> 5;
    const int lane = tid & 31;
    const int warp_m = wid >> 2;     // 0..1  -> 64-row strip
    const int warp_n = wid & 3;      // 0..3  -> 32-col strip
    const int ntile = blockIdx.x;    // 0..23 (fast dim -> A tile hot in L2)
    const int mtile = blockIdx.y;    // 0..127

    const __half* A  = g_ha  + (size_t)(mtile * 128) * DIM;
    const __half* Bh = g_whh + (size_t)(ntile * 128) * DIM;
    const __half* Bl = g_wlo + (size_t)(ntile * 128) * DIM;

    #pragma unroll
    for (int s = 0; s < NSTAGE - 1; s++) {
        load_stage(smem_base + s * STAGEB, A, Bh, Bl, s * 16, tid);
        CP_COMMIT();
    }

    float acc[4][4][4];
    #pragma unroll
    for (int mt = 0; mt < 4; mt++)
        #pragma unroll
        for (int nt = 0; nt < 4; nt++)
            #pragma unroll
            for (int r = 0; r < 4; r++) acc[mt][nt][r] = 0.f;

    const uint32_t a_base = (uint32_t)((warp_m * 64 + (lane & 15)) * PITCHB) + ((lane >> 4) << 4);
    const uint32_t b_base = (uint32_t)((warp_n * 32 + (lane & 7)) * PITCHB) + (((lane >> 3) & 1) << 4);

    for (int kc = 0; kc < NKC; kc++) {
        CP_WAIT2();
        __syncthreads();
        if (kc + NSTAGE - 1 < NKC)
            load_stage(smem_base + ((kc + NSTAGE - 1) & (NSTAGE - 1)) * STAGEB,
                       A, Bh, Bl, (kc + NSTAGE - 1) * 16, tid);
        CP_COMMIT();

        const uint32_t sb = smem_base + (kc & (NSTAGE - 1)) * STAGEB;
        uint32_t ah[4][4];
        #pragma unroll
        for (int mt = 0; mt < 4; mt++)
            ldm_x4(ah[mt], sb + OFF_A + a_base + mt * 16 * PITCHB);
        #pragma unroll
        for (int nt = 0; nt < 4; nt++) {
            uint32_t bh[2], bl[2];
            ldm_x2(bh, sb + OFF_BH + b_base + nt * 8 * PITCHB);
            ldm_x2(bl, sb + OFF_BL + b_base + nt * 8 * PITCHB);
            #pragma unroll
            for (int mt = 0; mt < 4; mt++) {
                mma16816(acc[mt][nt], ah[mt], bh);
                mma16816(acc[mt][nt], ah[mt], bl);
            }
        }
    }

    const int gid = lane >> 2, qid = lane & 3;
    #pragma unroll
    for (int mt = 0; mt < 4; mt++) {
        const int row0 = mtile * 128 + warp_m * 64 + mt * 16 + gid;
        #pragma unroll
        for (int nt = 0; nt < 4; nt++) {
            const int col = ntile * 128 + warp_n * 32 + nt * 8 + qid * 2;
            *(float2*)(g_qkva + (size_t)row0 * EDIM + col)       = make_float2(acc[mt][nt][0], acc[mt][nt][1]);
            *(float2*)(g_qkva + (size_t)(row0 + 8) * EDIM + col) = make_float2(acc[mt][nt][2], acc[mt][nt][3]);
        }
    }
}

// ===================== kernel 4: fused scan (chained carry lookback) ======
__global__ void __launch_bounds__(128) scan_fused_kernel(float* __restrict__ out) {
    const int tid = threadIdx.x;
    const int xc  = blockIdx.x;          // 0..3
    const int seg = blockIdx.y;          // 0..31
    const int b   = blockIdx.z;          // 0..3
    const int d0  = xc * 256 + tid * 2;
    const size_t tok0 = (size_t)b * SEQ + (size_t)seg * SEGL;

    // ---- pass 1: segment-local scan ----
    float pa0 = 1.f, pa1 = 1.f, y0 = 0.f, y1 = 0.f;
    const float* base_kv = g_qkva + tok0 * EDIM + DIM + d0;
    const float* base_av = g_qkva + tok0 * EDIM + 2 * DIM + d0;
    #pragma unroll 4
    for (int i = 0; i < SEGL; i++) {
        const float2 kv = *(const float2*)(base_kv + (size_t)i * EDIM);
        const float2 av = *(const float2*)(base_av + (size_t)i * EDIM);
        const float a0 = 1.0f / (1.0f + __expf(-av.x));
        const float a1 = 1.0f / (1.0f + __expf(-av.y));
        y0 = a0 * y0 + kv.x;  pa0 *= a0;
        y1 = a1 * y1 + kv.y;  pa1 *= a1;
    }

    // ---- lookback: wait predecessor's inclusive carry, publish ours ----
    const int fstride = DIM / 256;                    // 4
    const int fidx = (b * NSEG + seg) * fstride + xc;
    float c0 = 0.f, c1 = 0.f;
    if (seg > 0) {
        const int* flagp = &g_sflag[fidx - fstride];
        if (tid == 0) {
            unsigned v;
            do {
                asm volatile("ld.acquire.gpu.global.b32 %0, [%1];" : "=r"(v) : "l"(flagp) : "memory");
            } while (v == 0);
        }
        __syncthreads();
        const float2 cp = *(const float2*)&g_carry[(size_t)(b * NSEG + seg - 1) * DIM + d0];
        c0 = cp.x; c1 = cp.y;
    }
    float2 cinc = make_float2(pa0 * c0 + y0, pa1 * c1 + y1);
    if (seg < NSEG - 1) {
        *(float2*)&g_carry[(size_t)(b * NSEG + seg) * DIM + d0] = cinc;
        __threadfence();
        __syncthreads();
        if (tid == 0) {
            asm volatile("st.release.gpu.global.b32 [%0], %1;" :: "l"(&g_sflag[fidx]), "r"(1) : "memory");
        }
    }

    // ---- pass 2: recompute with carry-in, emit q*y ----
    const float* base_q = g_qkva + tok0 * EDIM + d0;
    float* outp = out + tok0 * DIM + d0;
    y0 = c0; y1 = c1;
    #pragma unroll 4
    for (int i = 0; i < SEGL; i++) {
        const float2 kv = *(const float2*)(base_kv + (size_t)i * EDIM);
        const float2 av = *(const float2*)(base_av + (size_t)i * EDIM);
        const float2 q  = *(const float2*)(base_q  + (size_t)i * EDIM);
        const float a0 = 1.0f / (1.0f + __expf(-av.x));
        const float a1 = 1.0f / (1.0f + __expf(-av.y));
        y0 = a0 * y0 + kv.x;
        y1 = a1 * y1 + kv.y;
        *(float2*)(outp + (size_t)i * DIM) = make_float2(q.x * y0, q.y * y1);
    }
}

// ===================== launcher =====================
extern "C" void kernel_launch(void* const* d_in, const int* in_sizes, int n_in,
                              void* d_out, int out_size) {
    const float* x     = (const float*)d_in[0];   // [4,4096,1024] f32
    const float* w     = (const float*)d_in[1];   // [3072,1024]  f32
    const float* gamma = (const float*)d_in[2];   // [1024]       f32
    float* out = (float*)d_out;

    cudaFuncSetAttribute(gemm_kernel, cudaFuncAttributeMaxDynamicSharedMemorySize, GEMM_SMEM);

    clear_flags_kernel<<<(BATCH * NSEG * (DIM / 256) + 127) / 128, 128>>>();
    rmsnorm_kernel<<<NTOK, 256>>>(x, gamma);
    wsplit_kernel<<<(EDIM * DIM / 4) / 256, 256>>>(w);
    gemm_kernel<<<dim3(EDIM / 128, NTOK / 128), 256, GEMM_SMEM>>>();
    scan_fused_kernel<<<dim3(DIM / 256, NSEG, BATCH), 128>>>(out);
}

// round 6
// speedup vs baseline: 2.0418x; 1.4528x over previous
#include <cuda_runtime.h>
#include <cuda_fp16.h>
#include <cstdint>

// ===================== problem constants =====================
#define NTOK  16384          // B*N tokens
#define DIM   1024
#define EDIM  3072           // 3*DIM
#define BATCH 4
#define SEQ   4096
#define NSEG  32
#define SEGL  128            // SEQ / NSEG

// ===================== device scratch (no cudaMalloc allowed) ==========
__device__ __half g_ha[(size_t)NTOK * DIM];    // fp16 activations
__device__ __half g_wh[(size_t)EDIM * DIM];    // fp16 weights
__device__ float  g_qkva[(size_t)NTOK * EDIM]; // GEMM output [tok][3d]
__device__ float  g_carry[BATCH * NSEG * DIM]; // inclusive carries per segment
__device__ int    g_sflag[BATCH * NSEG * (DIM / 256)];

// ===================== PTX helpers (all valid on compute_103) ==========
__device__ __forceinline__ uint32_t smem_u32(const void* p) {
    uint32_t r;
    asm("{ .reg .u64 t; cvta.to.shared.u64 t, %1; cvt.u32.u64 %0, t; }" : "=r"(r) : "l"(p));
    return r;
}
__device__ __forceinline__ void cp16(uint32_t dst, const void* src) {
    asm volatile("cp.async.cg.shared.global [%0], [%1], 16;" :: "r"(dst), "l"(src));
}
#define CP_COMMIT() asm volatile("cp.async.commit_group;" ::: "memory")
#define CP_WAIT2()  asm volatile("cp.async.wait_group 2;" ::: "memory")

__device__ __forceinline__ void ldm_x4(uint32_t* r, uint32_t addr) {
    asm volatile("ldmatrix.sync.aligned.m8n8.x4.shared.b16 {%0,%1,%2,%3}, [%4];"
                 : "=r"(r[0]), "=r"(r[1]), "=r"(r[2]), "=r"(r[3]) : "r"(addr));
}
__device__ __forceinline__ void ldm_x2(uint32_t* r, uint32_t addr) {
    asm volatile("ldmatrix.sync.aligned.m8n8.x2.shared.b16 {%0,%1}, [%2];"
                 : "=r"(r[0]), "=r"(r[1]) : "r"(addr));
}
__device__ __forceinline__ void mma16816(float* c, const uint32_t* a, const uint32_t* b) {
    asm volatile(
        "mma.sync.aligned.m16n8k16.row.col.f32.f16.f16.f32 "
        "{%0,%1,%2,%3}, {%4,%5,%6,%7}, {%8,%9}, {%0,%1,%2,%3};"
        : "+f"(c[0]), "+f"(c[1]), "+f"(c[2]), "+f"(c[3])
        : "r"(a[0]), "r"(a[1]), "r"(a[2]), "r"(a[3]), "r"(b[0]), "r"(b[1]));
}

// ===================== kernel 0: clear lookback flags =====================
__global__ void clear_flags_kernel() {
    const int i = blockIdx.x * 128 + threadIdx.x;
    if (i < BATCH * NSEG * (DIM / 256)) g_sflag[i] = 0;
}

// ===================== kernel 1: RMSNorm -> fp16 activations ==============
__global__ void rmsnorm_kernel(const float* __restrict__ x, const float* __restrict__ gamma) {
    __shared__ float red[8];
    const int tok = blockIdx.x;
    const int tid = threadIdx.x;   // 256 threads, 4 elems each
    float4 v = ((const float4*)(x + (size_t)tok * DIM))[tid];
    float s = v.x * v.x + v.y * v.y + v.z * v.z + v.w * v.w;
    #pragma unroll
    for (int o = 16; o; o >>= 1) s += __shfl_xor_sync(0xffffffffu, s, o);
    if ((tid & 31) == 0) red[tid >> 5] = s;
    __syncthreads();
    if (tid == 0) {
        float t = 0.f;
        #pragma unroll
        for (int i = 0; i < 8; i++) t += red[i];
        red[0] = 32.0f / fmaxf(sqrtf(t), 1e-12f);   // sqrt(DIM)=32
    }
    __syncthreads();
    const float scl = red[0];
    float4 g = ((const float4*)gamma)[tid];
    __half2* hh = (__half2*)(g_ha + (size_t)tok * DIM);
    hh[2 * tid]     = __floats2half2_rn(v.x * scl * g.x, v.y * scl * g.y);
    hh[2 * tid + 1] = __floats2half2_rn(v.z * scl * g.z, v.w * scl * g.w);
}

// ===================== kernel 2: weight convert -> fp16 ====================
__global__ void wconv_kernel(const float* __restrict__ w) {
    size_t i4 = (size_t)blockIdx.x * 256 + threadIdx.x;   // EDIM*DIM/4 float4s
    float4 v = ((const float4*)w)[i4];
    ((__half2*)g_wh)[2 * i4]     = __floats2half2_rn(v.x, v.y);
    ((__half2*)g_wh)[2 * i4 + 1] = __floats2half2_rn(v.z, v.w);
}

// ===================== kernel 3: HMMA GEMM (fp16, 1 MMA/microtile) ========
// qkva[m][e] = sum_d h[m][d]*w[e][d]; CTA 128x128, BK=32, 4-stage cp.async.
// SMEM stage: A / B, each 128 rows x 32 fp16, pitch 80 B (conflict-free ldmatrix).
#define PITCHB 80
#define TILEB  (128 * PITCHB)          // 10240
#define OFF_A  0
#define OFF_B  TILEB
#define STAGEB (2 * TILEB)             // 20480
#define NSTAGE 4
#define NKC    32                      // 1024 / 32
#define GEMM_SMEM (NSTAGE * STAGEB)    // 81920 -> 2 CTAs/SM (reg-bound)

__device__ __forceinline__ void load_stage(uint32_t sm_stage,
                                           const __half* A, const __half* B,
                                           int koff, int tid) {
    #pragma unroll
    for (int i = 0; i < 2; i++) {
        const int c   = tid + i * 256;       // 0..511
        const int row = c >> 2;              // 0..127
        const int kc4 = c & 3;               // four 16B chunks per 64B row
        const uint32_t so = (uint32_t)(row * PITCHB + kc4 * 16);
        const size_t   go = (size_t)row * DIM + koff + kc4 * 8;
        cp16(sm_stage + OFF_A + so, A + go);
        cp16(sm_stage + OFF_B + so, B + go);
    }
}

__global__ void __launch_bounds__(256, 2) gemm_kernel() {
    extern __shared__ char smem[];
    const uint32_t smem_base = smem_u32(smem);
    const int tid  = threadIdx.x;
    const int wid  = tid >> 5;
    const int lane = tid & 31;
    const int warp_m = wid >> 2;     // 0..1  -> 64-row strip
    const int warp_n = wid & 3;      // 0..3  -> 32-col strip
    const int ntile = blockIdx.x;    // 0..23 (fast dim -> A tile hot in L2)
    const int mtile = blockIdx.y;    // 0..127

    const __half* A = g_ha + (size_t)(mtile * 128) * DIM;
    const __half* B = g_wh + (size_t)(ntile * 128) * DIM;

    #pragma unroll
    for (int s = 0; s < NSTAGE - 1; s++) {
        load_stage(smem_base + s * STAGEB, A, B, s * 32, tid);
        CP_COMMIT();
    }

    float acc[4][4][4];
    #pragma unroll
    for (int mt = 0; mt < 4; mt++)
        #pragma unroll
        for (int nt = 0; nt < 4; nt++)
            #pragma unroll
            for (int r = 0; r < 4; r++) acc[mt][nt][r] = 0.f;

    const uint32_t a_base = (uint32_t)((warp_m * 64 + (lane & 15)) * PITCHB) + ((lane >> 4) << 4);
    const uint32_t b_base = (uint32_t)((warp_n * 32 + (lane & 7)) * PITCHB) + (((lane >> 3) & 1) << 4);

    for (int kc = 0; kc < NKC; kc++) {
        CP_WAIT2();                      // stage kc resident (<=2 groups pending)
        __syncthreads();
        if (kc + NSTAGE - 1 < NKC)
            load_stage(smem_base + ((kc + NSTAGE - 1) & (NSTAGE - 1)) * STAGEB,
                       A, B, (kc + NSTAGE - 1) * 32, tid);
        CP_COMMIT();

        const uint32_t sb = smem_base + (kc & (NSTAGE - 1)) * STAGEB;
        #pragma unroll
        for (int step = 0; step < 2; step++) {        // two K16 halves of BK=32
            uint32_t ah[4][4];
            #pragma unroll
            for (int mt = 0; mt < 4; mt++)
                ldm_x4(ah[mt], sb + OFF_A + a_base + step * 32 + mt * 16 * PITCHB);
            #pragma unroll
            for (int nt = 0; nt < 4; nt++) {
                uint32_t bf[2];
                ldm_x2(bf, sb + OFF_B + b_base + step * 32 + nt * 8 * PITCHB);
                #pragma unroll
                for (int mt = 0; mt < 4; mt++)
                    mma16816(acc[mt][nt], ah[mt], bf);
            }
        }
    }

    const int gid = lane >> 2, qid = lane & 3;
    #pragma unroll
    for (int mt = 0; mt < 4; mt++) {
        const int row0 = mtile * 128 + warp_m * 64 + mt * 16 + gid;
        #pragma unroll
        for (int nt = 0; nt < 4; nt++) {
            const int col = ntile * 128 + warp_n * 32 + nt * 8 + qid * 2;
            *(float2*)(g_qkva + (size_t)row0 * EDIM + col)       = make_float2(acc[mt][nt][0], acc[mt][nt][1]);
            *(float2*)(g_qkva + (size_t)(row0 + 8) * EDIM + col) = make_float2(acc[mt][nt][2], acc[mt][nt][3]);
        }
    }
}

// ===================== kernel 4: fused scan (chained carry lookback) ======
__global__ void __launch_bounds__(128) scan_fused_kernel(float* __restrict__ out) {
    const int tid = threadIdx.x;
    const int xc  = blockIdx.x;          // 0..3
    const int seg = blockIdx.y;          // 0..31
    const int b   = blockIdx.z;          // 0..3
    const int d0  = xc * 256 + tid * 2;
    const size_t tok0 = (size_t)b * SEQ + (size_t)seg * SEGL;

    // ---- pass 1: segment-local scan ----
    float pa0 = 1.f, pa1 = 1.f, y0 = 0.f, y1 = 0.f;
    const float* base_kv = g_qkva + tok0 * EDIM + DIM + d0;
    const float* base_av = g_qkva + tok0 * EDIM + 2 * DIM + d0;
    #pragma unroll 4
    for (int i = 0; i < SEGL; i++) {
        const float2 kv = *(const float2*)(base_kv + (size_t)i * EDIM);
        const float2 av = *(const float2*)(base_av + (size_t)i * EDIM);
        const float a0 = 1.0f / (1.0f + __expf(-av.x));
        const float a1 = 1.0f / (1.0f + __expf(-av.y));
        y0 = a0 * y0 + kv.x;  pa0 *= a0;
        y1 = a1 * y1 + kv.y;  pa1 *= a1;
    }

    // ---- lookback: wait predecessor's inclusive carry, publish ours ----
    const int fstride = DIM / 256;                    // 4
    const int fidx = (b * NSEG + seg) * fstride + xc;
    float c0 = 0.f, c1 = 0.f;
    if (seg > 0) {
        const int* flagp = &g_sflag[fidx - fstride];
        if (tid == 0) {
            unsigned v;
            do {
                asm volatile("ld.acquire.gpu.global.b32 %0, [%1];" : "=r"(v) : "l"(flagp) : "memory");
            } while (v == 0);
        }
        __syncthreads();
        const float2 cp = *(const float2*)&g_carry[(size_t)(b * NSEG + seg - 1) * DIM + d0];
        c0 = cp.x; c1 = cp.y;
    }
    float2 cinc = make_float2(pa0 * c0 + y0, pa1 * c1 + y1);
    if (seg < NSEG - 1) {
        *(float2*)&g_carry[(size_t)(b * NSEG + seg) * DIM + d0] = cinc;
        __threadfence();
        __syncthreads();
        if (tid == 0) {
            asm volatile("st.release.gpu.global.b32 [%0], %1;" :: "l"(&g_sflag[fidx]), "r"(1) : "memory");
        }
    }

    // ---- pass 2: recompute with carry-in, emit q*y ----
    const float* base_q = g_qkva + tok0 * EDIM + d0;
    float* outp = out + tok0 * DIM + d0;
    y0 = c0; y1 = c1;
    #pragma unroll 4
    for (int i = 0; i < SEGL; i++) {
        const float2 kv = *(const float2*)(base_kv + (size_t)i * EDIM);
        const float2 av = *(const float2*)(base_av + (size_t)i * EDIM);
        const float2 q  = *(const float2*)(base_q  + (size_t)i * EDIM);
        const float a0 = 1.0f / (1.0f + __expf(-av.x));
        const float a1 = 1.0f / (1.0f + __expf(-av.y));
        y0 = a0 * y0 + kv.x;
        y1 = a1 * y1 + kv.y;
        *(float2*)(outp + (size_t)i * DIM) = make_float2(q.x * y0, q.y * y1);
    }
}

// ===================== launcher =====================
extern "C" void kernel_launch(void* const* d_in, const int* in_sizes, int n_in,
                              void* d_out, int out_size) {
    const float* x     = (const float*)d_in[0];   // [4,4096,1024] f32
    const float* w     = (const float*)d_in[1];   // [3072,1024]  f32
    const float* gamma = (const float*)d_in[2];   // [1024]       f32
    float* out = (float*)d_out;

    cudaFuncSetAttribute(gemm_kernel, cudaFuncAttributeMaxDynamicSharedMemorySize, GEMM_SMEM);

    clear_flags_kernel<<<(BATCH * NSEG * (DIM / 256) + 127) / 128, 128>>>();
    rmsnorm_kernel<<<NTOK, 256>>>(x, gamma);
    wconv_kernel<<<(EDIM * DIM / 4) / 256, 256>>>(w);
    gemm_kernel<<<dim3(EDIM / 128, NTOK / 128), 256, GEMM_SMEM>>>();
    scan_fused_kernel<<<dim3(DIM / 256, NSEG, BATCH), 128>>>(out);
}